// round 5
// baseline (speedup 1.0000x reference)
#include <cuda_runtime.h>
#include <cuda_bf16.h>
#include <cstdint>

// Problem constants
#define Tn 1024
#define Dn 2048
#define Hn 7168
#define En 8
#define Kn 2
#define Pn (Tn * Kn)                   // 2048 (token,k) pairs
#define TILE_M 128
#define MAX_SLOTS (Pn + En * TILE_M)   // 3072
#define MAX_TILES (Pn / TILE_M + En)   // 24

#define G1_KIT (Dn / 32)               // 64 K-chunks of 32
#define G2_KIT (Hn / 32)               // 224 K-chunks of 32
#define WN (En * Hn * Dn)              // weight elements per tensor

// Dynamic smem: 3 stages x 32KB + 1KB alignment slack
#define SMEM_REQ (3 * 32768 + 1024)

// Scratch (device globals; no allocation allowed)
__device__ int   g_slot_token[MAX_SLOTS];
__device__ float g_slot_w[MAX_SLOTS];
__device__ int   g_tile_expert[MAX_TILES];
__device__ int   g_tile_base[MAX_TILES];
// bf16 hi/lo planes for everything the GEMMs consume
__device__ __align__(16) unsigned short g_x_hi[(size_t)Tn * Dn];
__device__ __align__(16) unsigned short g_x_lo[(size_t)Tn * Dn];
__device__ __align__(16) unsigned short g_w1_hi[(size_t)WN];
__device__ __align__(16) unsigned short g_w1_lo[(size_t)WN];
__device__ __align__(16) unsigned short g_w2_hi[(size_t)WN];
__device__ __align__(16) unsigned short g_w2_lo[(size_t)WN];
__device__ __align__(16) unsigned short g_w3_hi[(size_t)WN];
__device__ __align__(16) unsigned short g_w3_lo[(size_t)WN];
__device__ __align__(16) unsigned short g_hact_hi[(size_t)MAX_SLOTS * Hn];
__device__ __align__(16) unsigned short g_hact_lo[(size_t)MAX_SLOTS * Hn];

// ---------------------------------------------------------------------------
// Helpers
// ---------------------------------------------------------------------------
__device__ __forceinline__ uint32_t smem_u32(const void* p) {
    uint32_t a;
    asm("{ .reg .u64 t; cvta.to.shared.u64 t, %1; cvt.u32.u64 %0, t; }"
        : "=r"(a) : "l"(p));
    return a;
}

__device__ __forceinline__ uint32_t sw128(uint32_t o) {
    return o ^ (((o >> 7) & 7u) << 4);
}
__device__ __forceinline__ uint32_t sw256(uint32_t o) {
    return o ^ (((o >> 8) & 7u) << 4);
}

__device__ __forceinline__ void cpa16(uint32_t dst, const void* src, uint32_t sz) {
    asm volatile("cp.async.cg.shared.global [%0], [%1], 16, %2;"
                 :: "r"(dst), "l"(src), "r"(sz) : "memory");
}
#define CP_COMMIT() asm volatile("cp.async.commit_group;" ::: "memory")
#define CP_WAIT1()  asm volatile("cp.async.wait_group 1;" ::: "memory")

__device__ __forceinline__ void ldsm4(uint32_t* r, uint32_t a) {
    asm volatile("ldmatrix.sync.aligned.m8n8.x4.shared.b16 {%0,%1,%2,%3}, [%4];"
        : "=r"(r[0]), "=r"(r[1]), "=r"(r[2]), "=r"(r[3]) : "r"(a));
}
__device__ __forceinline__ void ldsm4t(uint32_t* r, uint32_t a) {
    asm volatile("ldmatrix.sync.aligned.m8n8.x4.trans.shared.b16 {%0,%1,%2,%3}, [%4];"
        : "=r"(r[0]), "=r"(r[1]), "=r"(r[2]), "=r"(r[3]) : "r"(a));
}
__device__ __forceinline__ void mma16816(float* c, const uint32_t* a,
                                         uint32_t b0, uint32_t b1) {
    asm volatile(
        "mma.sync.aligned.m16n8k16.row.col.f32.bf16.bf16.f32 "
        "{%0,%1,%2,%3}, {%4,%5,%6,%7}, {%8,%9}, {%0,%1,%2,%3};"
        : "+f"(c[0]), "+f"(c[1]), "+f"(c[2]), "+f"(c[3])
        : "r"(a[0]), "r"(a[1]), "r"(a[2]), "r"(a[3]), "r"(b0), "r"(b1));
}

// bf16 split: hi = truncate(v) (exact in bf16 and fp32), lo = rn(v - hi)
__device__ __forceinline__ uint32_t pack_hi(float a, float b) {
    return (__float_as_uint(a) >> 16) | (__float_as_uint(b) & 0xffff0000u);
}
__device__ __forceinline__ uint32_t pack_lo(float a, float b) {
    float ha = __uint_as_float(__float_as_uint(a) & 0xffff0000u);
    float hb = __uint_as_float(__float_as_uint(b) & 0xffff0000u);
    unsigned short la = __bfloat16_as_ushort(__float2bfloat16(a - ha));
    unsigned short lb = __bfloat16_as_ushort(__float2bfloat16(b - hb));
    return (uint32_t)la | ((uint32_t)lb << 16);
}

// ---------------------------------------------------------------------------
// Split: fp32 -> bf16 hi/lo planes (streaming, DRAM-bound)
// which: 0=w1, 1=w2, 2=w3, 3=x
// ---------------------------------------------------------------------------
__global__ void split_kernel(const float4* __restrict__ src, int which, int n4) {
    uint2* hi;
    uint2* lo;
    switch (which) {
        case 0:  hi = (uint2*)g_w1_hi; lo = (uint2*)g_w1_lo; break;
        case 1:  hi = (uint2*)g_w2_hi; lo = (uint2*)g_w2_lo; break;
        case 2:  hi = (uint2*)g_w3_hi; lo = (uint2*)g_w3_lo; break;
        default: hi = (uint2*)g_x_hi;  lo = (uint2*)g_x_lo;  break;
    }
    for (int i = blockIdx.x * blockDim.x + threadIdx.x; i < n4;
         i += gridDim.x * blockDim.x) {
        float4 v = __ldg(src + i);
        hi[i] = make_uint2(pack_hi(v.x, v.y), pack_hi(v.z, v.w));
        lo[i] = make_uint2(pack_lo(v.x, v.y), pack_lo(v.z, v.w));
    }
}

// ---------------------------------------------------------------------------
// Routing
// ---------------------------------------------------------------------------
__global__ void route_kernel(const int* __restrict__ sel,
                             const float* __restrict__ wts) {
    __shared__ int s_e[Pn];
    __shared__ int s_cnt[En];
    __shared__ int s_base[En];
    int tid = threadIdx.x;

    if (tid < En) s_cnt[tid] = 0;
    __syncthreads();
    for (int i = tid; i < Pn; i += blockDim.x) {
        int e = sel[i];
        s_e[i] = e;
        atomicAdd(&s_cnt[e], 1);
    }
    __syncthreads();
    if (tid == 0) {
        int base = 0, tile = 0;
        for (int e = 0; e < En; e++) {
            s_base[e] = base;
            int padded = ((s_cnt[e] + TILE_M - 1) / TILE_M) * TILE_M;
            for (int m = 0; m < padded; m += TILE_M) {
                g_tile_expert[tile] = e;
                g_tile_base[tile]   = base + m;
                tile++;
            }
            base += padded;
        }
        for (; tile < MAX_TILES; tile++) g_tile_expert[tile] = -1;
    }
    __syncthreads();
    for (int s = tid; s < MAX_SLOTS; s += blockDim.x) g_slot_token[s] = -1;
    __syncthreads();
    for (int i = tid; i < Pn; i += blockDim.x) {
        int e = s_e[i];
        int rank = 0;
        for (int j = 0; j < i; j++) rank += (s_e[j] == e) ? 1 : 0;
        int slot = s_base[e] + rank;
        g_slot_token[slot] = i / Kn;
        g_slot_w[slot]     = wts[i];
    }
}

__global__ void zero_kernel(float* __restrict__ out) {
    int i = blockIdx.x * blockDim.x + threadIdx.x;
    out[i] = 0.0f;
}

// ---------------------------------------------------------------------------
// GEMM1: hact[slot, h0+c] = silu(x.W1^T) * (x.W3^T)
// C tile 128x128 (n 0-63 gate / 64-127 up), BK=32, 3-stage cp.async pipeline.
// SMEM stage (32KB): A 128x[hi 64B|lo 64B], B 128x[hi 64B|lo 64B].
// ---------------------------------------------------------------------------
__global__ __launch_bounds__(256, 2) void gemm1_kernel(
    const float* __restrict__ x_unused) {
    int e = g_tile_expert[blockIdx.x];
    if (e < 0) return;
    int base = g_tile_base[blockIdx.x];
    int h0 = blockIdx.y * 64;

    extern __shared__ char dsm[];
    __shared__ int s_tok[TILE_M];
    uint32_t raw = smem_u32(dsm);
    uint32_t sb = (raw + 1023u) & ~1023u;
    char* sp = dsm + (sb - raw);

    int tid = threadIdx.x;
    if (tid < TILE_M) s_tok[tid] = g_slot_token[base + tid];
    __syncthreads();

    const int warp = tid >> 5, lane = tid & 31;
    const int wm = warp & 3, wn = warp >> 2;   // 4m x 2n, warp tile 32x64

    // cp.async mapping: thread t covers row t>>1, plane t&1 (4 granules each side)
    const int row = tid >> 1, pl = tid & 1;
    const int tok = s_tok[row];
    const unsigned short* aS =
        (pl ? g_x_lo : g_x_hi) + (size_t)(tok < 0 ? 0 : tok) * Dn;
    const uint32_t asz = (tok >= 0) ? 16u : 0u;
    const unsigned short* bS = (row < 64)
        ? (pl ? g_w1_lo : g_w1_hi) + ((size_t)e * Hn + h0 + row) * Dn
        : (pl ? g_w3_lo : g_w3_hi) + ((size_t)e * Hn + h0 + row - 64) * Dn;
    const uint32_t aoff = (uint32_t)row * 128u + (uint32_t)pl * 64u;

    // ldmatrix lane offsets
    const uint32_t a_m  = (uint32_t)(lane & 15);
    const uint32_t a_kc = (uint32_t)(lane >> 4);
    const uint32_t b_n  = (uint32_t)((lane & 7) | ((lane >> 4) << 3));
    const uint32_t b_kc = (uint32_t)((lane >> 3) & 1);

    float C[2][8][4];
#pragma unroll
    for (int i = 0; i < 2; i++)
#pragma unroll
        for (int j = 0; j < 8; j++)
#pragma unroll
            for (int k = 0; k < 4; k++) C[i][j][k] = 0.f;

#define LOAD1(c, st) do {                                                   \
    uint32_t Ab = sb + (st) * 32768u;                                       \
    uint32_t Bb = Ab + 16384u;                                              \
    const unsigned short* as = aS + (c) * 32;                               \
    const unsigned short* bs = bS + (c) * 32;                               \
    _Pragma("unroll")                                                       \
    for (int g = 0; g < 4; g++) {                                           \
        cpa16(Ab + sw128(aoff + g * 16), as + g * 8, asz);                  \
        cpa16(Bb + sw128(aoff + g * 16), bs + g * 8, 16u);                  \
    }                                                                       \
    CP_COMMIT();                                                            \
} while (0)

#define COMP1(st) do {                                                      \
    uint32_t Au = sb + (st) * 32768u;                                       \
    uint32_t Bu = Au + 16384u;                                              \
    _Pragma("unroll")                                                       \
    for (int k16 = 0; k16 < 2; k16++) {                                     \
        uint32_t aH[2][4], aL[2][4];                                        \
        _Pragma("unroll")                                                   \
        for (int mt = 0; mt < 2; mt++) {                                    \
            uint32_t o = (uint32_t)(wm * 32 + mt * 16 + a_m) * 128u + k16 * 32u + a_kc * 16u; \
            ldsm4(aH[mt], Au + sw128(o));                                   \
            ldsm4(aL[mt], Au + sw128(o + 64));                              \
        }                                                                   \
        _Pragma("unroll")                                                   \
        for (int ng = 0; ng < 4; ng++) {                                    \
            uint32_t o = (uint32_t)(wn * 64 + ng * 16 + b_n) * 128u + k16 * 32u + b_kc * 16u; \
            uint32_t bH[4], bL[4];                                          \
            ldsm4(bH, Bu + sw128(o));                                       \
            ldsm4(bL, Bu + sw128(o + 64));                                  \
            _Pragma("unroll")                                               \
            for (int mt = 0; mt < 2; mt++) {                                \
                mma16816(C[mt][2 * ng],     aH[mt], bH[0], bH[1]);          \
                mma16816(C[mt][2 * ng + 1], aH[mt], bH[2], bH[3]);          \
                mma16816(C[mt][2 * ng],     aL[mt], bH[0], bH[1]);          \
                mma16816(C[mt][2 * ng + 1], aL[mt], bH[2], bH[3]);          \
                mma16816(C[mt][2 * ng],     aH[mt], bL[0], bL[1]);          \
                mma16816(C[mt][2 * ng + 1], aH[mt], bL[2], bL[3]);          \
            }                                                               \
        }                                                                   \
    }                                                                       \
} while (0)

    LOAD1(0, 0);
    LOAD1(1, 1);
    int st = 0;
    for (int c = 0; c < G1_KIT; c++) {
        CP_WAIT1();
        __syncthreads();
        COMP1(st);
        if (c + 2 < G1_KIT) {
            int st2 = st + 2;
            if (st2 >= 3) st2 -= 3;
            LOAD1(c + 2, st2);
        }
        st++;
        if (st == 3) st = 0;
    }
    __syncthreads();

    // C -> smem fp32 [128][132]
    float* sc = (float*)sp;
#pragma unroll
    for (int mt = 0; mt < 2; mt++)
#pragma unroll
        for (int nt = 0; nt < 8; nt++) {
            int r0 = wm * 32 + mt * 16 + (lane >> 2);
            int cc = wn * 64 + nt * 8 + (lane & 3) * 2;
            sc[r0 * 132 + cc]       = C[mt][nt][0];
            sc[r0 * 132 + cc + 1]   = C[mt][nt][1];
            sc[(r0 + 8) * 132 + cc]     = C[mt][nt][2];
            sc[(r0 + 8) * 132 + cc + 1] = C[mt][nt][3];
        }
    __syncthreads();

    // SiLU(gate)*up -> g_hact hi/lo planes
    {
        int m = tid >> 1, coff = (tid & 1) * 32;
        size_t orow = (size_t)(base + m) * Hn + h0 + coff;
#pragma unroll
        for (int j = 0; j < 32; j += 4) {
            float v[4];
#pragma unroll
            for (int jj = 0; jj < 4; jj++) {
                float g = sc[m * 132 + coff + j + jj];
                float u = sc[m * 132 + 64 + coff + j + jj];
                v[jj] = g / (1.f + __expf(-g)) * u;
            }
            *(uint2*)(g_hact_hi + orow + j) =
                make_uint2(pack_hi(v[0], v[1]), pack_hi(v[2], v[3]));
            *(uint2*)(g_hact_lo + orow + j) =
                make_uint2(pack_lo(v[0], v[1]), pack_lo(v[2], v[3]));
        }
    }
#undef LOAD1
#undef COMP1
}

// ---------------------------------------------------------------------------
// GEMM2: out[tok, d0+c] += w * sum_h hact[slot,h] * w2[e,h,d0+c]
// A = hact planes ([m][k] 128B rows).  B = w2 planes in native [k][n]:
// Bh/Bl 32x256B rows, loaded with ldmatrix.trans. 3-stage cp.async.
// ---------------------------------------------------------------------------
__global__ __launch_bounds__(256, 2) void gemm2_kernel(
    float* __restrict__ out) {
    int e = g_tile_expert[blockIdx.x];
    if (e < 0) return;
    int base = g_tile_base[blockIdx.x];
    int d0 = blockIdx.y * 128;

    extern __shared__ char dsm[];
    __shared__ int   s_tok[TILE_M];
    __shared__ float s_w[TILE_M];
    uint32_t raw = smem_u32(dsm);
    uint32_t sb = (raw + 1023u) & ~1023u;
    char* sp = dsm + (sb - raw);

    int tid = threadIdx.x;
    if (tid < TILE_M) {
        s_tok[tid] = g_slot_token[base + tid];
        s_w[tid]   = g_slot_w[base + tid];
    }
    __syncthreads();

    const int warp = tid >> 5, lane = tid & 31;
    const int wm = warp & 3, wn = warp >> 2;

    // A cp.async mapping: row t>>1, plane t&1
    const int row = tid >> 1, pl = tid & 1;
    const unsigned short* aS =
        (pl ? g_hact_lo : g_hact_hi) + (size_t)(base + row) * Hn;
    const uint32_t aoff = (uint32_t)row * 128u + (uint32_t)pl * 64u;

    // B cp.async mapping: k-row t>>3 (0..31), seg q = t&7 (2 granules/plane)
    const int kr = tid >> 3, q = tid & 7;
    const unsigned short* bhS = g_w2_hi + ((size_t)e * Hn + kr) * Dn + d0 + q * 16;
    const unsigned short* blS = g_w2_lo + ((size_t)e * Hn + kr) * Dn + d0 + q * 16;
    const uint32_t boff = (uint32_t)kr * 256u + (uint32_t)q * 32u;

    // ldmatrix lane offsets
    const uint32_t a_m  = (uint32_t)(lane & 15);
    const uint32_t a_kc = (uint32_t)(lane >> 4);
    const uint32_t t_k  = (uint32_t)((lane & 7) | (((lane >> 3) & 1) << 3));
    const uint32_t t_n8 = (uint32_t)(lane >> 4);

    float C[2][8][4];
#pragma unroll
    for (int i = 0; i < 2; i++)
#pragma unroll
        for (int j = 0; j < 8; j++)
#pragma unroll
            for (int k = 0; k < 4; k++) C[i][j][k] = 0.f;

#define LOAD2(c, st) do {                                                   \
    uint32_t Ab = sb + (st) * 32768u;                                       \
    uint32_t Bh = Ab + 16384u;                                              \
    uint32_t Bl = Ab + 24576u;                                              \
    const unsigned short* as = aS + (c) * 32;                               \
    _Pragma("unroll")                                                       \
    for (int g = 0; g < 4; g++)                                             \
        cpa16(Ab + sw128(aoff + g * 16), as + g * 8, 16u);                  \
    const unsigned short* bh = bhS + (size_t)(c) * 32 * Dn;                 \
    const unsigned short* bl = blS + (size_t)(c) * 32 * Dn;                 \
    cpa16(Bh + sw256(boff),      bh,     16u);                              \
    cpa16(Bh + sw256(boff + 16), bh + 8, 16u);                              \
    cpa16(Bl + sw256(boff),      bl,     16u);                              \
    cpa16(Bl + sw256(boff + 16), bl + 8, 16u);                              \
    CP_COMMIT();                                                            \
} while (0)

#define COMP2(st) do {                                                      \
    uint32_t Au  = sb + (st) * 32768u;                                      \
    uint32_t Bhu = Au + 16384u;                                             \
    uint32_t Blu = Au + 24576u;                                             \
    _Pragma("unroll")                                                       \
    for (int k16 = 0; k16 < 2; k16++) {                                     \
        uint32_t aH[2][4], aL[2][4];                                        \
        _Pragma("unroll")                                                   \
        for (int mt = 0; mt < 2; mt++) {                                    \
            uint32_t o = (uint32_t)(wm * 32 + mt * 16 + a_m) * 128u + k16 * 32u + a_kc * 16u; \
            ldsm4(aH[mt], Au + sw128(o));                                   \
            ldsm4(aL[mt], Au + sw128(o + 64));                              \
        }                                                                   \
        _Pragma("unroll")                                                   \
        for (int ng = 0; ng < 4; ng++) {                                    \
            uint32_t o = (k16 * 16u + t_k) * 256u                           \
                       + (uint32_t)(wn * 64 + ng * 16) * 2u + t_n8 * 16u;   \
            uint32_t bH[4], bL[4];                                          \
            ldsm4t(bH, Bhu + sw256(o));                                     \
            ldsm4t(bL, Blu + sw256(o));                                     \
            _Pragma("unroll")                                               \
            for (int mt = 0; mt < 2; mt++) {                                \
                mma16816(C[mt][2 * ng],     aH[mt], bH[0], bH[1]);          \
                mma16816(C[mt][2 * ng + 1], aH[mt], bH[2], bH[3]);          \
                mma16816(C[mt][2 * ng],     aL[mt], bH[0], bH[1]);          \
                mma16816(C[mt][2 * ng + 1], aL[mt], bH[2], bH[3]);          \
                mma16816(C[mt][2 * ng],     aH[mt], bL[0], bL[1]);          \
                mma16816(C[mt][2 * ng + 1], aH[mt], bL[2], bL[3]);          \
            }                                                               \
        }                                                                   \
    }                                                                       \
} while (0)

    LOAD2(0, 0);
    LOAD2(1, 1);
    int st = 0;
    for (int c = 0; c < G2_KIT; c++) {
        CP_WAIT1();
        __syncthreads();
        COMP2(st);
        if (c + 2 < G2_KIT) {
            int st2 = st + 2;
            if (st2 >= 3) st2 -= 3;
            LOAD2(c + 2, st2);
        }
        st++;
        if (st == 3) st = 0;
    }
    __syncthreads();

    // C -> smem fp32 [128][132]
    float* sc = (float*)sp;
#pragma unroll
    for (int mt = 0; mt < 2; mt++)
#pragma unroll
        for (int nt = 0; nt < 8; nt++) {
            int r0 = wm * 32 + mt * 16 + (lane >> 2);
            int cc = wn * 64 + nt * 8 + (lane & 3) * 2;
            sc[r0 * 132 + cc]       = C[mt][nt][0];
            sc[r0 * 132 + cc + 1]   = C[mt][nt][1];
            sc[(r0 + 8) * 132 + cc]     = C[mt][nt][2];
            sc[(r0 + 8) * 132 + cc + 1] = C[mt][nt][3];
        }
    __syncthreads();

    // weighted accumulate (K=2 commutative adds -> deterministic)
    {
        int m = tid >> 1, coff = (tid & 1) * 64;
        int tok = s_tok[m];
        if (tok >= 0) {
            float wgt = s_w[m];
            float* dst = out + (size_t)tok * Dn + d0 + coff;
#pragma unroll 8
            for (int j = 0; j < 64; j++)
                atomicAdd(dst + j, wgt * sc[m * 132 + coff + j]);
        }
    }
#undef LOAD2
#undef COMP2
}

// ---------------------------------------------------------------------------
extern "C" void kernel_launch(void* const* d_in, const int* in_sizes, int n_in,
                              void* d_out, int out_size) {
    const float* x   = (const float*)d_in[0];
    const float* wts = (const float*)d_in[1];
    const int*   sel = (const int*)d_in[2];
    const float* w1  = (const float*)d_in[3];
    const float* w2  = (const float*)d_in[4];
    const float* w3  = (const float*)d_in[5];
    float* out = (float*)d_out;

    cudaFuncSetAttribute(gemm1_kernel,
                         cudaFuncAttributeMaxDynamicSharedMemorySize, SMEM_REQ);
    cudaFuncSetAttribute(gemm2_kernel,
                         cudaFuncAttributeMaxDynamicSharedMemorySize, SMEM_REQ);

    route_kernel<<<1, 1024>>>(sel, wts);
    zero_kernel<<<(Tn * Dn) / 256, 256>>>(out);
    split_kernel<<<8192, 256>>>((const float4*)w1, 0, WN / 4);
    split_kernel<<<8192, 256>>>((const float4*)w2, 1, WN / 4);
    split_kernel<<<8192, 256>>>((const float4*)w3, 2, WN / 4);
    split_kernel<<<2048, 256>>>((const float4*)x, 3, (Tn * Dn) / 4);
    // tile index fastest: all M-tiles of one weight tile run concurrently,
    // weights stream from DRAM once and reuse via L2.
    gemm1_kernel<<<dim3(MAX_TILES, Hn / 64), 256, SMEM_REQ>>>(x);
    gemm2_kernel<<<dim3(MAX_TILES, Dn / 128), 256, SMEM_REQ>>>(out);
}

// round 6
// speedup vs baseline: 1.2016x; 1.2016x over previous
#include <cuda_runtime.h>
#include <cuda_bf16.h>
#include <cstdint>

// Problem constants
#define Tn 1024
#define Dn 2048
#define Hn 7168
#define En 8
#define Kn 2
#define Pn (Tn * Kn)                   // 2048 (token,k) pairs
#define TILE_M 128
#define MAX_SLOTS (Pn + En * TILE_M)   // 3072
#define MAX_TILES (Pn / TILE_M + En)   // 24

#define G1_KIT (Dn / 32)               // 64 K-chunks of 32
#define G2_KIT (Hn / 32)               // 224 K-chunks of 32

// Dynamic smem: 2 stages x 32KB (mainloop) / 128x132 fp32 (epilogue) + slack
#define SMEM_REQ 68608

// Scratch (device globals; no allocation allowed)
__device__ int   g_slot_token[MAX_SLOTS];
__device__ float g_slot_w[MAX_SLOTS];
__device__ int   g_tile_expert[MAX_TILES];
__device__ int   g_tile_base[MAX_TILES];
// bf16 hi/lo planes for the A-side operands only (x is tiny; hact is produced split)
__device__ __align__(16) unsigned short g_x_hi[(size_t)Tn * Dn];
__device__ __align__(16) unsigned short g_x_lo[(size_t)Tn * Dn];
__device__ __align__(16) unsigned short g_hact_hi[(size_t)MAX_SLOTS * Hn];
__device__ __align__(16) unsigned short g_hact_lo[(size_t)MAX_SLOTS * Hn];

// ---------------------------------------------------------------------------
// Helpers
// ---------------------------------------------------------------------------
__device__ __forceinline__ uint32_t smem_u32(const void* p) {
    uint32_t a;
    asm("{ .reg .u64 t; cvta.to.shared.u64 t, %1; cvt.u32.u64 %0, t; }"
        : "=r"(a) : "l"(p));
    return a;
}

__device__ __forceinline__ uint32_t sw128(uint32_t o) {
    return o ^ (((o >> 7) & 7u) << 4);
}
__device__ __forceinline__ uint32_t sw256(uint32_t o) {
    return o ^ (((o >> 8) & 7u) << 4);
}

__device__ __forceinline__ void cpa16(uint32_t dst, const void* src, uint32_t sz) {
    asm volatile("cp.async.cg.shared.global [%0], [%1], 16, %2;"
                 :: "r"(dst), "l"(src), "r"(sz) : "memory");
}
#define CP_COMMIT() asm volatile("cp.async.commit_group;" ::: "memory")
#define CP_WAIT0()  asm volatile("cp.async.wait_group 0;" ::: "memory")

__device__ __forceinline__ void ldsm4(uint32_t* r, uint32_t a) {
    asm volatile("ldmatrix.sync.aligned.m8n8.x4.shared.b16 {%0,%1,%2,%3}, [%4];"
        : "=r"(r[0]), "=r"(r[1]), "=r"(r[2]), "=r"(r[3]) : "r"(a));
}
__device__ __forceinline__ void ldsm4t(uint32_t* r, uint32_t a) {
    asm volatile("ldmatrix.sync.aligned.m8n8.x4.trans.shared.b16 {%0,%1,%2,%3}, [%4];"
        : "=r"(r[0]), "=r"(r[1]), "=r"(r[2]), "=r"(r[3]) : "r"(a));
}
__device__ __forceinline__ void mma16816(float* c, const uint32_t* a,
                                         uint32_t b0, uint32_t b1) {
    asm volatile(
        "mma.sync.aligned.m16n8k16.row.col.f32.bf16.bf16.f32 "
        "{%0,%1,%2,%3}, {%4,%5,%6,%7}, {%8,%9}, {%0,%1,%2,%3};"
        : "+f"(c[0]), "+f"(c[1]), "+f"(c[2]), "+f"(c[3])
        : "r"(a[0]), "r"(a[1]), "r"(a[2]), "r"(a[3]), "r"(b0), "r"(b1));
}

// bf16 split: hi = truncate(v) (exact in bf16 and fp32), lo = rn(v - hi)
__device__ __forceinline__ uint32_t pack_hi(float a, float b) {
    return (__float_as_uint(a) >> 16) | (__float_as_uint(b) & 0xffff0000u);
}
__device__ __forceinline__ uint32_t pack_lo(float a, float b) {
    float ha = __uint_as_float(__float_as_uint(a) & 0xffff0000u);
    float hb = __uint_as_float(__float_as_uint(b) & 0xffff0000u);
    unsigned short la = __bfloat16_as_ushort(__float2bfloat16(a - ha));
    unsigned short lb = __bfloat16_as_ushort(__float2bfloat16(b - hb));
    return (uint32_t)la | ((uint32_t)lb << 16);
}

// ---------------------------------------------------------------------------
// x split: fp32 -> bf16 hi/lo planes (8 MB, ~8us)
// ---------------------------------------------------------------------------
__global__ void splitx_kernel(const float4* __restrict__ src, int n4) {
    int i = blockIdx.x * blockDim.x + threadIdx.x;
    if (i < n4) {
        float4 v = __ldg(src + i);
        ((uint2*)g_x_hi)[i] = make_uint2(pack_hi(v.x, v.y), pack_hi(v.z, v.w));
        ((uint2*)g_x_lo)[i] = make_uint2(pack_lo(v.x, v.y), pack_lo(v.z, v.w));
    }
}

// ---------------------------------------------------------------------------
// Routing
// ---------------------------------------------------------------------------
__global__ void route_kernel(const int* __restrict__ sel,
                             const float* __restrict__ wts) {
    __shared__ int s_e[Pn];
    __shared__ int s_cnt[En];
    __shared__ int s_base[En];
    int tid = threadIdx.x;

    if (tid < En) s_cnt[tid] = 0;
    __syncthreads();
    for (int i = tid; i < Pn; i += blockDim.x) {
        int e = sel[i];
        s_e[i] = e;
        atomicAdd(&s_cnt[e], 1);
    }
    __syncthreads();
    if (tid == 0) {
        int base = 0, tile = 0;
        for (int e = 0; e < En; e++) {
            s_base[e] = base;
            int padded = ((s_cnt[e] + TILE_M - 1) / TILE_M) * TILE_M;
            for (int m = 0; m < padded; m += TILE_M) {
                g_tile_expert[tile] = e;
                g_tile_base[tile]   = base + m;
                tile++;
            }
            base += padded;
        }
        for (; tile < MAX_TILES; tile++) g_tile_expert[tile] = -1;
    }
    __syncthreads();
    for (int s = tid; s < MAX_SLOTS; s += blockDim.x) g_slot_token[s] = -1;
    __syncthreads();
    for (int i = tid; i < Pn; i += blockDim.x) {
        int e = s_e[i];
        int rank = 0;
        for (int j = 0; j < i; j++) rank += (s_e[j] == e) ? 1 : 0;
        int slot = s_base[e] + rank;
        g_slot_token[slot] = i / Kn;
        g_slot_w[slot]     = wts[i];
    }
}

__global__ void zero_kernel(float* __restrict__ out) {
    int i = blockIdx.x * blockDim.x + threadIdx.x;
    out[i] = 0.0f;
}

// ---------------------------------------------------------------------------
// GEMM1: hact[slot, h0+c] = silu(x.W1^T) * (x.W3^T)
// CTA 128x128 (n 0-63 gate / 64-127 up), BK=32, 4 warps, warp tile 64x64.
// A (x planes) via cp.async; B (w1/w3 fp32) via reg-staged LDG + convert + STS.
// ---------------------------------------------------------------------------
__global__ __launch_bounds__(128, 2) void gemm1_kernel(
    const float* __restrict__ w1,
    const float* __restrict__ w3) {
    int e = g_tile_expert[blockIdx.x];
    if (e < 0) return;
    int base = g_tile_base[blockIdx.x];
    int h0 = blockIdx.y * 64;

    extern __shared__ char dsm[];
    __shared__ int s_tok[TILE_M];
    uint32_t raw = smem_u32(dsm);
    uint32_t sb = (raw + 1023u) & ~1023u;
    char* sp = dsm + (sb - raw);

    int tid = threadIdx.x;
    s_tok[tid] = g_slot_token[base + tid];
    __syncthreads();

    const int warp = tid >> 5, lane = tid & 31;
    const int wm = warp & 1, wn = warp >> 1;   // 2m x 2n, warp tile 64x64

    // A cp.async: thread t owns row t (hi 64B + lo 64B per chunk)
    const int tok = s_tok[tid];
    const unsigned short* aHs = g_x_hi + (size_t)(tok < 0 ? 0 : tok) * Dn;
    const unsigned short* aLs = g_x_lo + (size_t)(tok < 0 ? 0 : tok) * Dn;
    const uint32_t asz = (tok >= 0) ? 16u : 0u;
    const uint32_t aoff = (uint32_t)tid * 128u;

    // B LDG: thread t owns weight row t (w1 rows 0-63, w3 rows 64-127)
    const float* bP = (tid < 64)
        ? w1 + ((size_t)e * Hn + h0 + tid) * Dn
        : w3 + ((size_t)e * Hn + h0 + tid - 64) * Dn;
    const uint32_t boff = (uint32_t)tid * 128u;

    // ldmatrix lane offsets
    const uint32_t a_m  = (uint32_t)(lane & 15);
    const uint32_t a_kc = (uint32_t)(lane >> 4);
    const uint32_t b_n  = (uint32_t)((lane & 7) | ((lane >> 4) << 3));
    const uint32_t b_kc = (uint32_t)((lane >> 3) & 1);

    float C[4][8][4];
#pragma unroll
    for (int i = 0; i < 4; i++)
#pragma unroll
        for (int j = 0; j < 8; j++)
#pragma unroll
            for (int k = 0; k < 4; k++) C[i][j][k] = 0.f;

    float4 Br[8];

#define LDGB1(c) do {                                                       \
    const float4* q = (const float4*)(bP + (size_t)(c) * 32);               \
    _Pragma("unroll")                                                       \
    for (int i = 0; i < 8; i++) Br[i] = __ldg(q + i);                       \
} while (0)

#define CPA1(c, st) do {                                                    \
    uint32_t Ab = sb + (st) * 32768u;                                       \
    const unsigned short* ah = aHs + (c) * 32;                              \
    const unsigned short* al = aLs + (c) * 32;                              \
    _Pragma("unroll")                                                       \
    for (int g = 0; g < 4; g++) {                                           \
        cpa16(Ab + sw128(aoff + g * 16), ah + g * 8, asz);                  \
        cpa16(Ab + sw128(aoff + 64 + g * 16), al + g * 8, asz);             \
    }                                                                       \
    CP_COMMIT();                                                            \
} while (0)

#define STSB1(st) do {                                                      \
    char* Bb = sp + (st) * 32768 + 16384;                                   \
    _Pragma("unroll")                                                       \
    for (int g = 0; g < 4; g++) {                                           \
        float4 v0 = Br[2 * g], v1 = Br[2 * g + 1];                          \
        uint4 h = make_uint4(pack_hi(v0.x, v0.y), pack_hi(v0.z, v0.w),      \
                             pack_hi(v1.x, v1.y), pack_hi(v1.z, v1.w));     \
        uint4 l = make_uint4(pack_lo(v0.x, v0.y), pack_lo(v0.z, v0.w),      \
                             pack_lo(v1.x, v1.y), pack_lo(v1.z, v1.w));     \
        *(uint4*)(Bb + sw128(boff + g * 16)) = h;                           \
        *(uint4*)(Bb + sw128(boff + 64 + g * 16)) = l;                      \
    }                                                                       \
} while (0)

#define COMP1(st) do {                                                      \
    uint32_t Au = sb + (st) * 32768u;                                       \
    uint32_t Bu = Au + 16384u;                                              \
    _Pragma("unroll")                                                       \
    for (int k16 = 0; k16 < 2; k16++) {                                     \
        uint32_t aH[4][4], aL[4][4];                                        \
        _Pragma("unroll")                                                   \
        for (int mt = 0; mt < 4; mt++) {                                    \
            uint32_t o = (uint32_t)(wm * 64 + mt * 16 + a_m) * 128u + k16 * 32u + a_kc * 16u; \
            ldsm4(aH[mt], Au + sw128(o));                                   \
            ldsm4(aL[mt], Au + sw128(o + 64));                              \
        }                                                                   \
        _Pragma("unroll")                                                   \
        for (int ng = 0; ng < 4; ng++) {                                    \
            uint32_t o = (uint32_t)(wn * 64 + ng * 16 + b_n) * 128u + k16 * 32u + b_kc * 16u; \
            uint32_t bH[4], bL[4];                                          \
            ldsm4(bH, Bu + sw128(o));                                       \
            ldsm4(bL, Bu + sw128(o + 64));                                  \
            _Pragma("unroll")                                               \
            for (int mt = 0; mt < 4; mt++) {                                \
                mma16816(C[mt][2 * ng],     aH[mt], bH[0], bH[1]);          \
                mma16816(C[mt][2 * ng + 1], aH[mt], bH[2], bH[3]);          \
                mma16816(C[mt][2 * ng],     aL[mt], bH[0], bH[1]);          \
                mma16816(C[mt][2 * ng + 1], aL[mt], bH[2], bH[3]);          \
                mma16816(C[mt][2 * ng],     aH[mt], bL[0], bL[1]);          \
                mma16816(C[mt][2 * ng + 1], aH[mt], bL[2], bL[3]);          \
            }                                                               \
        }                                                                   \
    }                                                                       \
} while (0)

    LDGB1(0);
    CPA1(0, 0);
    STSB1(0);
    LDGB1(1);
    for (int c = 0; c < G1_KIT; c++) {
        int st = c & 1;
        CP_WAIT0();
        __syncthreads();
        if (c + 1 < G1_KIT) CPA1(c + 1, st ^ 1);
        COMP1(st);
        if (c + 1 < G1_KIT) STSB1(st ^ 1);
        if (c + 2 < G1_KIT) LDGB1(c + 2);
    }
    __syncthreads();

    // C -> smem fp32 [128][132]
    float* sc = (float*)sp;
#pragma unroll
    for (int mt = 0; mt < 4; mt++)
#pragma unroll
        for (int nt = 0; nt < 8; nt++) {
            int r0 = wm * 64 + mt * 16 + (lane >> 2);
            int cc = wn * 64 + nt * 8 + (lane & 3) * 2;
            sc[r0 * 132 + cc]       = C[mt][nt][0];
            sc[r0 * 132 + cc + 1]   = C[mt][nt][1];
            sc[(r0 + 8) * 132 + cc]     = C[mt][nt][2];
            sc[(r0 + 8) * 132 + cc + 1] = C[mt][nt][3];
        }
    __syncthreads();

    // SiLU(gate)*up -> g_hact hi/lo planes; thread t owns row t (64 outputs)
    {
        size_t orow = (size_t)(base + tid) * Hn + h0;
#pragma unroll
        for (int j = 0; j < 64; j += 4) {
            float v[4];
#pragma unroll
            for (int jj = 0; jj < 4; jj++) {
                float g = sc[tid * 132 + j + jj];
                float u = sc[tid * 132 + 64 + j + jj];
                v[jj] = g / (1.f + __expf(-g)) * u;
            }
            *(uint2*)(g_hact_hi + orow + j) =
                make_uint2(pack_hi(v[0], v[1]), pack_hi(v[2], v[3]));
            *(uint2*)(g_hact_lo + orow + j) =
                make_uint2(pack_lo(v[0], v[1]), pack_lo(v[2], v[3]));
        }
    }
#undef LDGB1
#undef CPA1
#undef STSB1
#undef COMP1
}

// ---------------------------------------------------------------------------
// GEMM2: out[tok, d0+c] += w * sum_h hact[slot,h] * w2[e,h,d0+c]
// CTA 128x128, 4 warps, warp tile 64x64. A = hact planes via cp.async;
// B = w2 fp32 in native [k][n] via LDG+convert, ldmatrix.trans read.
// ---------------------------------------------------------------------------
__global__ __launch_bounds__(128, 2) void gemm2_kernel(
    const float* __restrict__ w2,
    float* __restrict__ out) {
    int e = g_tile_expert[blockIdx.x];
    if (e < 0) return;
    int base = g_tile_base[blockIdx.x];
    int d0 = blockIdx.y * 128;

    extern __shared__ char dsm[];
    __shared__ int   s_tok[TILE_M];
    __shared__ float s_w[TILE_M];
    uint32_t raw = smem_u32(dsm);
    uint32_t sb = (raw + 1023u) & ~1023u;
    char* sp = dsm + (sb - raw);

    int tid = threadIdx.x;
    s_tok[tid] = g_slot_token[base + tid];
    s_w[tid]   = g_slot_w[base + tid];
    __syncthreads();

    const int warp = tid >> 5, lane = tid & 31;
    const int wm = warp & 1, wn = warp >> 1;

    // A cp.async: thread t owns row t
    const unsigned short* aHs = g_hact_hi + (size_t)(base + tid) * Hn;
    const unsigned short* aLs = g_hact_lo + (size_t)(base + tid) * Hn;
    const uint32_t aoff = (uint32_t)tid * 128u;

    // B LDG: k-row t>>2 (0..31), d-segment (t&3)*32
    const int kr = tid >> 2, ds = (tid & 3) * 32;
    const float* wP = w2 + ((size_t)e * Hn + kr) * Dn + d0 + ds;
    const uint32_t boff = (uint32_t)kr * 256u + (uint32_t)ds * 2u;

    // ldmatrix lane offsets
    const uint32_t a_m  = (uint32_t)(lane & 15);
    const uint32_t a_kc = (uint32_t)(lane >> 4);
    const uint32_t t_k  = (uint32_t)((lane & 7) | (((lane >> 3) & 1) << 3));
    const uint32_t t_n8 = (uint32_t)(lane >> 4);

    float C[4][8][4];
#pragma unroll
    for (int i = 0; i < 4; i++)
#pragma unroll
        for (int j = 0; j < 8; j++)
#pragma unroll
            for (int k = 0; k < 4; k++) C[i][j][k] = 0.f;

    float4 Br[8];

#define LDGB2(c) do {                                                       \
    const float4* q = (const float4*)(wP + (size_t)(c) * 32 * Dn);          \
    _Pragma("unroll")                                                       \
    for (int i = 0; i < 8; i++) Br[i] = __ldg(q + i);                       \
} while (0)

#define CPA2(c, st) do {                                                    \
    uint32_t Ab = sb + (st) * 32768u;                                       \
    const unsigned short* ah = aHs + (c) * 32;                              \
    const unsigned short* al = aLs + (c) * 32;                              \
    _Pragma("unroll")                                                       \
    for (int g = 0; g < 4; g++) {                                           \
        cpa16(Ab + sw128(aoff + g * 16), ah + g * 8, 16u);                  \
        cpa16(Ab + sw128(aoff + 64 + g * 16), al + g * 8, 16u);             \
    }                                                                       \
    CP_COMMIT();                                                            \
} while (0)

#define STSB2(st) do {                                                      \
    char* Bh = sp + (st) * 32768 + 16384;                                   \
    char* Bl = sp + (st) * 32768 + 24576;                                   \
    _Pragma("unroll")                                                       \
    for (int g = 0; g < 4; g++) {                                           \
        float4 v0 = Br[2 * g], v1 = Br[2 * g + 1];                          \
        uint4 h = make_uint4(pack_hi(v0.x, v0.y), pack_hi(v0.z, v0.w),      \
                             pack_hi(v1.x, v1.y), pack_hi(v1.z, v1.w));     \
        uint4 l = make_uint4(pack_lo(v0.x, v0.y), pack_lo(v0.z, v0.w),      \
                             pack_lo(v1.x, v1.y), pack_lo(v1.z, v1.w));     \
        *(uint4*)(Bh + sw256(boff + g * 16)) = h;                           \
        *(uint4*)(Bl + sw256(boff + g * 16)) = l;                           \
    }                                                                       \
} while (0)

#define COMP2(st) do {                                                      \
    uint32_t Au  = sb + (st) * 32768u;                                      \
    uint32_t Bhu = Au + 16384u;                                             \
    uint32_t Blu = Au + 24576u;                                             \
    _Pragma("unroll")                                                       \
    for (int k16 = 0; k16 < 2; k16++) {                                     \
        uint32_t aH[4][4], aL[4][4];                                        \
        _Pragma("unroll")                                                   \
        for (int mt = 0; mt < 4; mt++) {                                    \
            uint32_t o = (uint32_t)(wm * 64 + mt * 16 + a_m) * 128u + k16 * 32u + a_kc * 16u; \
            ldsm4(aH[mt], Au + sw128(o));                                   \
            ldsm4(aL[mt], Au + sw128(o + 64));                              \
        }                                                                   \
        _Pragma("unroll")                                                   \
        for (int ng = 0; ng < 4; ng++) {                                    \
            uint32_t o = (k16 * 16u + t_k) * 256u                           \
                       + (uint32_t)(wn * 64 + ng * 16) * 2u + t_n8 * 16u;   \
            uint32_t bH[4], bL[4];                                          \
            ldsm4t(bH, Bhu + sw256(o));                                     \
            ldsm4t(bL, Blu + sw256(o));                                     \
            _Pragma("unroll")                                               \
            for (int mt = 0; mt < 4; mt++) {                                \
                mma16816(C[mt][2 * ng],     aH[mt], bH[0], bH[1]);          \
                mma16816(C[mt][2 * ng + 1], aH[mt], bH[2], bH[3]);          \
                mma16816(C[mt][2 * ng],     aL[mt], bH[0], bH[1]);          \
                mma16816(C[mt][2 * ng + 1], aL[mt], bH[2], bH[3]);          \
                mma16816(C[mt][2 * ng],     aH[mt], bL[0], bL[1]);          \
                mma16816(C[mt][2 * ng + 1], aH[mt], bL[2], bL[3]);          \
            }                                                               \
        }                                                                   \
    }                                                                       \
} while (0)

    LDGB2(0);
    CPA2(0, 0);
    STSB2(0);
    LDGB2(1);
    for (int c = 0; c < G2_KIT; c++) {
        int st = c & 1;
        CP_WAIT0();
        __syncthreads();
        if (c + 1 < G2_KIT) CPA2(c + 1, st ^ 1);
        COMP2(st);
        if (c + 1 < G2_KIT) STSB2(st ^ 1);
        if (c + 2 < G2_KIT) LDGB2(c + 2);
    }
    __syncthreads();

    // C -> smem fp32 [128][132]
    float* sc = (float*)sp;
#pragma unroll
    for (int mt = 0; mt < 4; mt++)
#pragma unroll
        for (int nt = 0; nt < 8; nt++) {
            int r0 = wm * 64 + mt * 16 + (lane >> 2);
            int cc = wn * 64 + nt * 8 + (lane & 3) * 2;
            sc[r0 * 132 + cc]       = C[mt][nt][0];
            sc[r0 * 132 + cc + 1]   = C[mt][nt][1];
            sc[(r0 + 8) * 132 + cc]     = C[mt][nt][2];
            sc[(r0 + 8) * 132 + cc + 1] = C[mt][nt][3];
        }
    __syncthreads();

    // weighted accumulate (K=2 commutative adds -> deterministic)
    {
        int tok = s_tok[tid];
        if (tok >= 0) {
            float wgt = s_w[tid];
            float* dst = out + (size_t)tok * Dn + d0;
#pragma unroll 8
            for (int j = 0; j < 128; j++)
                atomicAdd(dst + j, wgt * sc[tid * 132 + j]);
        }
    }
#undef LDGB2
#undef CPA2
#undef STSB2
#undef COMP2
}

// ---------------------------------------------------------------------------
extern "C" void kernel_launch(void* const* d_in, const int* in_sizes, int n_in,
                              void* d_out, int out_size) {
    const float* x   = (const float*)d_in[0];
    const float* wts = (const float*)d_in[1];
    const int*   sel = (const int*)d_in[2];
    const float* w1  = (const float*)d_in[3];
    const float* w2  = (const float*)d_in[4];
    const float* w3  = (const float*)d_in[5];
    float* out = (float*)d_out;

    cudaFuncSetAttribute(gemm1_kernel,
                         cudaFuncAttributeMaxDynamicSharedMemorySize, SMEM_REQ);
    cudaFuncSetAttribute(gemm2_kernel,
                         cudaFuncAttributeMaxDynamicSharedMemorySize, SMEM_REQ);

    route_kernel<<<1, 1024>>>(sel, wts);
    zero_kernel<<<(Tn * Dn) / 256, 256>>>(out);
    splitx_kernel<<<(Tn * Dn) / 1024, 256>>>((const float4*)x, (Tn * Dn) / 4);
    // tile index fastest: all M-tiles of one weight tile run concurrently,
    // weights stream from DRAM once and reuse via L2.
    gemm1_kernel<<<dim3(MAX_TILES, Hn / 64), 128, SMEM_REQ>>>(w1, w3);
    gemm2_kernel<<<dim3(MAX_TILES, Dn / 128), 128, SMEM_REQ>>>(w2, out);
}